// round 7
// baseline (speedup 1.0000x reference)
#include <cuda_runtime.h>
#include <cuda_bf16.h>
#include <cstdint>

// Greedy CTC decode (split + PDL overlap):
//   emission: [T, V=128] fp32
//   out (fp32, 3*T): [ idx(0:T) | keep(T:2T) | path_score(2T:3T) ]
//
// Kernel 1: warp handles 8 consecutive rows; 8 front-batched LDG.128 (MLP=8).
//           Per-row warp argmax with 2 REDUX collectives (max key, then min
//           index over tied lanes = first occurrence, matching jnp.argmax).
//           Triggers programmatic launch completion immediately so the
//           dependent dedup grid can ramp under our tail.
// Kernel 2: vectorized dedup; gated by cudaGridDependencySynchronize().

#define V 128
#define BLANK 0
#define WARPS_PER_BLOCK 8
#define ROWS_PER_WARP 8
#define ROWS_PER_BLOCK (WARPS_PER_BLOCK * ROWS_PER_WARP)   // 64
#define FULL_MASK 0xFFFFFFFFu

// Order-preserving fp32 bits -> u32 map and inverse.
__device__ __forceinline__ unsigned fmono(float f) {
    unsigned b = __float_as_uint(f);
    return b ^ ((unsigned)((int)b >> 31) | 0x80000000u);
}
__device__ __forceinline__ float funmono(unsigned u) {
    unsigned b = u ^ ((unsigned)((int)(~u) >> 31) | 0x80000000u);
    return __uint_as_float(b);
}

__global__ void __launch_bounds__(WARPS_PER_BLOCK * 32)
ctc_argmax_kernel(const float* __restrict__ em,
                  float* __restrict__ out_idx,
                  float* __restrict__ out_max,
                  int rows)
{
#if __CUDA_ARCH__ >= 900
    cudaTriggerProgrammaticLaunchCompletion();
#endif
    const int lane = threadIdx.x & 31;
    const int base = (blockIdx.x * WARPS_PER_BLOCK + (threadIdx.x >> 5)) * ROWS_PER_WARP;
    if (base >= rows) return;

    // Front-batched loads: 8 independent LDG.128, 4KB contiguous per warp.
    float4 v[ROWS_PER_WARP];
    #pragma unroll
    for (int k = 0; k < ROWS_PER_WARP; k++) {
        v[k] = reinterpret_cast<const float4*>(em + (size_t)(base + k) * V)[lane];
    }

    float res_idx[ROWS_PER_WARP];
    float res_max[ROWS_PER_WARP];

    #pragma unroll
    for (int k = 0; k < ROWS_PER_WARP; k++) {
        // Local argmax over this lane's 4 columns (strict > keeps earliest).
        float best = v[k].x; int bi = lane * 4;
        if (v[k].y > best) { best = v[k].y; bi = lane * 4 + 1; }
        if (v[k].z > best) { best = v[k].z; bi = lane * 4 + 2; }
        if (v[k].w > best) { best = v[k].w; bi = lane * 4 + 3; }

        unsigned key  = fmono(best);
        unsigned wmax = __reduce_max_sync(FULL_MASK, key);
        unsigned cand = (key == wmax) ? (unsigned)bi : 0x7FFFFFFFu;
        unsigned widx = __reduce_min_sync(FULL_MASK, cand);  // lowest col of ties

        res_idx[k] = (float)widx;
        res_max[k] = funmono(wmax);
    }

    if (lane == 0) {
        // base is a multiple of 8 -> 16B-aligned float4 stores
        reinterpret_cast<float4*>(out_idx + base)[0] =
            make_float4(res_idx[0], res_idx[1], res_idx[2], res_idx[3]);
        reinterpret_cast<float4*>(out_idx + base)[1] =
            make_float4(res_idx[4], res_idx[5], res_idx[6], res_idx[7]);
        reinterpret_cast<float4*>(out_max + base)[0] =
            make_float4(res_max[0], res_max[1], res_max[2], res_max[3]);
        reinterpret_cast<float4*>(out_max + base)[1] =
            make_float4(res_max[4], res_max[5], res_max[6], res_max[7]);
    }
}

__global__ void __launch_bounds__(256)
ctc_dedup_kernel(const float* __restrict__ idx_f,   // out[0:T]
                 float* __restrict__ keep_f,        // out[T:2T]
                 float* __restrict__ score_f,       // out[2T:3T]: max in, score out
                 int rows)
{
    // Prologue (index math) runs while argmax is still in flight.
    const int lane = threadIdx.x & 31;
    int i = blockIdx.x * blockDim.x + threadIdx.x;  // float4 index
    int t = i * 4;

#if __CUDA_ARCH__ >= 900
    cudaGridDependencySynchronize();   // wait: argmax results now visible
#endif
    if (t >= rows) return;

    float4 c = reinterpret_cast<const float4*>(idx_f)[i];
    float4 s = reinterpret_cast<const float4*>(score_f)[i];

    // prev for element t: lane-1's c.w covers all lanes except lane 0.
    float prev0 = __shfl_up_sync(FULL_MASK, c.w, 1);
    if (lane == 0) prev0 = (t > 0) ? idx_f[t - 1] : -1.0f;

    bool k0 = (c.x != prev0) && (c.x != (float)BLANK);
    bool k1 = (c.y != c.x)   && (c.y != (float)BLANK);
    bool k2 = (c.z != c.y)   && (c.z != (float)BLANK);
    bool k3 = (c.w != c.z)   && (c.w != (float)BLANK);

    reinterpret_cast<float4*>(keep_f)[i] =
        make_float4(k0 ? 1.0f : 0.0f, k1 ? 1.0f : 0.0f,
                    k2 ? 1.0f : 0.0f, k3 ? 1.0f : 0.0f);
    reinterpret_cast<float4*>(score_f)[i] =
        make_float4(k0 ? s.x : 0.0f, k1 ? s.y : 0.0f,
                    k2 ? s.z : 0.0f, k3 ? s.w : 0.0f);
}

extern "C" void kernel_launch(void* const* d_in, const int* in_sizes, int n_in,
                              void* d_out, int out_size)
{
    const float* em = (const float*)d_in[0];
    float* out = (float*)d_out;

    const int rows = in_sizes[0] / V;            // T = 1048576
    float* out_idx   = out;                      // [0:T)
    float* out_keep  = out + rows;               // [T:2T)
    float* out_score = out + 2 * (size_t)rows;   // [2T:3T)

    {
        dim3 block(WARPS_PER_BLOCK * 32);
        dim3 grid(rows / ROWS_PER_BLOCK);        // exact: 16384
        ctc_argmax_kernel<<<grid, block>>>(em, out_idx, out_score, rows);
    }
    {
        int nvec = rows / 4;                     // 262144
        cudaLaunchConfig_t cfg = {};
        cfg.gridDim  = dim3(nvec / 256);         // exact: 1024
        cfg.blockDim = dim3(256);
        cfg.dynamicSmemBytes = 0;
        cfg.stream = 0;
        cudaLaunchAttribute attr[1];
        attr[0].id = cudaLaunchAttributeProgrammaticStreamSerialization;
        attr[0].val.programmaticStreamSerializationAllowed = 1;
        cfg.attrs = attr;
        cfg.numAttrs = 1;
        cudaLaunchKernelEx(&cfg, ctc_dedup_kernel,
                           (const float*)out_idx, out_keep, out_score, rows);
    }
}

// round 8
// speedup vs baseline: 1.0011x; 1.0011x over previous
#include <cuda_runtime.h>
#include <cuda_bf16.h>
#include <cstdint>

// Greedy CTC decode (split):
//   emission: [T, V=128] fp32
//   out (fp32, 3*T): [ idx(0:T) | keep(T:2T) | path_score(2T:3T) ]
//
// Kernel 1: warp handles 8 consecutive rows; 8 front-batched LDG.128 (MLP=8).
//           Per-row warp argmax with 2 REDUX collectives (max key, then min
//           index over tied lanes = first occurrence, matching jnp.argmax).
//           512-thread blocks (128 rows/block) to reduce CTA churn.
// Kernel 2: dedup, 8 elements/thread: 4 independent float4 loads in flight
//           (MLP=4), prev via __shfl_up, one lane-0 scalar load per warp.

#define V 128
#define BLANK 0
#define WARPS_PER_BLOCK 16
#define ROWS_PER_WARP 8
#define ROWS_PER_BLOCK (WARPS_PER_BLOCK * ROWS_PER_WARP)   // 128
#define FULL_MASK 0xFFFFFFFFu

// Order-preserving fp32 bits -> u32 map and inverse.
__device__ __forceinline__ unsigned fmono(float f) {
    unsigned b = __float_as_uint(f);
    return b ^ ((unsigned)((int)b >> 31) | 0x80000000u);
}
__device__ __forceinline__ float funmono(unsigned u) {
    unsigned b = u ^ ((unsigned)((int)(~u) >> 31) | 0x80000000u);
    return __uint_as_float(b);
}

__global__ void __launch_bounds__(WARPS_PER_BLOCK * 32)
ctc_argmax_kernel(const float* __restrict__ em,
                  float* __restrict__ out_idx,
                  float* __restrict__ out_max,
                  int rows)
{
    const int lane = threadIdx.x & 31;
    const int base = (blockIdx.x * WARPS_PER_BLOCK + (threadIdx.x >> 5)) * ROWS_PER_WARP;
    if (base >= rows) return;

    // Front-batched loads: 8 independent LDG.128, 4KB contiguous per warp.
    float4 v[ROWS_PER_WARP];
    #pragma unroll
    for (int k = 0; k < ROWS_PER_WARP; k++) {
        v[k] = reinterpret_cast<const float4*>(em + (size_t)(base + k) * V)[lane];
    }

    float res_idx[ROWS_PER_WARP];
    float res_max[ROWS_PER_WARP];

    #pragma unroll
    for (int k = 0; k < ROWS_PER_WARP; k++) {
        // Local argmax over this lane's 4 columns (strict > keeps earliest).
        float best = v[k].x; int bi = lane * 4;
        if (v[k].y > best) { best = v[k].y; bi = lane * 4 + 1; }
        if (v[k].z > best) { best = v[k].z; bi = lane * 4 + 2; }
        if (v[k].w > best) { best = v[k].w; bi = lane * 4 + 3; }

        unsigned key  = fmono(best);
        unsigned wmax = __reduce_max_sync(FULL_MASK, key);
        unsigned cand = (key == wmax) ? (unsigned)bi : 0x7FFFFFFFu;
        unsigned widx = __reduce_min_sync(FULL_MASK, cand);  // lowest col of ties

        res_idx[k] = (float)widx;
        res_max[k] = funmono(wmax);
    }

    if (lane == 0) {
        // base is a multiple of 8 -> 16B-aligned float4 stores
        reinterpret_cast<float4*>(out_idx + base)[0] =
            make_float4(res_idx[0], res_idx[1], res_idx[2], res_idx[3]);
        reinterpret_cast<float4*>(out_idx + base)[1] =
            make_float4(res_idx[4], res_idx[5], res_idx[6], res_idx[7]);
        reinterpret_cast<float4*>(out_max + base)[0] =
            make_float4(res_max[0], res_max[1], res_max[2], res_max[3]);
        reinterpret_cast<float4*>(out_max + base)[1] =
            make_float4(res_max[4], res_max[5], res_max[6], res_max[7]);
    }
}

__global__ void __launch_bounds__(256)
ctc_dedup_kernel(const float* __restrict__ idx_f,   // out[0:T]
                 float* __restrict__ keep_f,        // out[T:2T]
                 float* __restrict__ score_f,       // out[2T:3T]: max in, score out
                 int rows)
{
    const int lane = threadIdx.x & 31;
    int i = blockIdx.x * blockDim.x + threadIdx.x;  // 8-elem chunk index
    int t = i * 8;
    if (t >= rows) return;

    // 4 independent loads in flight (MLP=4).
    float4 c0 = reinterpret_cast<const float4*>(idx_f)[i * 2];
    float4 c1 = reinterpret_cast<const float4*>(idx_f)[i * 2 + 1];
    float4 s0 = reinterpret_cast<const float4*>(score_f)[i * 2];
    float4 s1 = reinterpret_cast<const float4*>(score_f)[i * 2 + 1];

    // prev for element t: lane-1's c1.w covers all lanes except lane 0.
    float prev0 = __shfl_up_sync(FULL_MASK, c1.w, 1);
    if (lane == 0) prev0 = (t > 0) ? idx_f[t - 1] : -1.0f;

    bool k0 = (c0.x != prev0) && (c0.x != (float)BLANK);
    bool k1 = (c0.y != c0.x)  && (c0.y != (float)BLANK);
    bool k2 = (c0.z != c0.y)  && (c0.z != (float)BLANK);
    bool k3 = (c0.w != c0.z)  && (c0.w != (float)BLANK);
    bool k4 = (c1.x != c0.w)  && (c1.x != (float)BLANK);
    bool k5 = (c1.y != c1.x)  && (c1.y != (float)BLANK);
    bool k6 = (c1.z != c1.y)  && (c1.z != (float)BLANK);
    bool k7 = (c1.w != c1.z)  && (c1.w != (float)BLANK);

    reinterpret_cast<float4*>(keep_f)[i * 2] =
        make_float4(k0 ? 1.0f : 0.0f, k1 ? 1.0f : 0.0f,
                    k2 ? 1.0f : 0.0f, k3 ? 1.0f : 0.0f);
    reinterpret_cast<float4*>(keep_f)[i * 2 + 1] =
        make_float4(k4 ? 1.0f : 0.0f, k5 ? 1.0f : 0.0f,
                    k6 ? 1.0f : 0.0f, k7 ? 1.0f : 0.0f);
    reinterpret_cast<float4*>(score_f)[i * 2] =
        make_float4(k0 ? s0.x : 0.0f, k1 ? s0.y : 0.0f,
                    k2 ? s0.z : 0.0f, k3 ? s0.w : 0.0f);
    reinterpret_cast<float4*>(score_f)[i * 2 + 1] =
        make_float4(k4 ? s1.x : 0.0f, k5 ? s1.y : 0.0f,
                    k6 ? s1.z : 0.0f, k7 ? s1.w : 0.0f);
}

extern "C" void kernel_launch(void* const* d_in, const int* in_sizes, int n_in,
                              void* d_out, int out_size)
{
    const float* em = (const float*)d_in[0];
    float* out = (float*)d_out;

    const int rows = in_sizes[0] / V;            // T = 1048576
    float* out_idx   = out;                      // [0:T)
    float* out_keep  = out + rows;               // [T:2T)
    float* out_score = out + 2 * (size_t)rows;   // [2T:3T)

    {
        dim3 block(WARPS_PER_BLOCK * 32);        // 512
        dim3 grid(rows / ROWS_PER_BLOCK);        // exact: 8192
        ctc_argmax_kernel<<<grid, block>>>(em, out_idx, out_score, rows);
    }
    {
        int nchunk = rows / 8;                   // 131072
        dim3 block(256);
        dim3 grid(nchunk / 256);                 // exact: 512
        ctc_dedup_kernel<<<grid, block>>>(out_idx, out_keep, out_score, rows);
    }
}

// round 9
// speedup vs baseline: 1.0530x; 1.0518x over previous
#include <cuda_runtime.h>
#include <cuda_bf16.h>
#include <cstdint>

// Greedy CTC decode, single fused kernel, NO synchronization:
//   emission: [T, V=128] fp32
//   out (fp32, 3*T): [ idx(0:T) | keep(T:2T) | path_score(2T:3T) ]
//
// Each warp owns 8 consecutive rows and additionally loads row base-1 (the
// neighboring warp's last row -> L2-deduped, ~no extra DRAM traffic).
// 9 front-batched LDG.128 (MLP=9). Per-row warp argmax uses 2 REDUX
// collectives: max over monotone key, then min over tied lanes' column
// indices (= first occurrence, exactly matching jnp.argmax). Dedup runs
// inline with the carried prev; lane 0 stores idx/keep/score as float4s.

#define V 128
#define BLANK 0
#define WARPS_PER_BLOCK 8
#define ROWS_PER_WARP 8
#define ROWS_PER_BLOCK (WARPS_PER_BLOCK * ROWS_PER_WARP)   // 64
#define FULL_MASK 0xFFFFFFFFu

// Order-preserving fp32 bits -> u32 map and inverse.
__device__ __forceinline__ unsigned fmono(float f) {
    unsigned b = __float_as_uint(f);
    return b ^ ((unsigned)((int)b >> 31) | 0x80000000u);
}
__device__ __forceinline__ float funmono(unsigned u) {
    unsigned b = u ^ ((unsigned)((int)(~u) >> 31) | 0x80000000u);
    return __uint_as_float(b);
}

// Warp argmax of one row held as lane-local float4. Uniform result on all lanes.
__device__ __forceinline__ void warp_row_argmax(const float4 v, int lane,
                                                float& o_idx, float& o_max)
{
    float best = v.x; int bi = lane * 4;
    if (v.y > best) { best = v.y; bi = lane * 4 + 1; }
    if (v.z > best) { best = v.z; bi = lane * 4 + 2; }
    if (v.w > best) { best = v.w; bi = lane * 4 + 3; }

    unsigned key  = fmono(best);
    unsigned wmax = __reduce_max_sync(FULL_MASK, key);
    unsigned cand = (key == wmax) ? (unsigned)bi : 0x7FFFFFFFu;
    unsigned widx = __reduce_min_sync(FULL_MASK, cand);  // lowest col of ties

    o_idx = (float)widx;
    o_max = funmono(wmax);
}

__global__ void __launch_bounds__(WARPS_PER_BLOCK * 32)
ctc_fused_kernel(const float* __restrict__ em,
                 float* __restrict__ out_idx,
                 float* __restrict__ out_keep,
                 float* __restrict__ out_score)
{
    const int lane = threadIdx.x & 31;
    const int base = (blockIdx.x * WARPS_PER_BLOCK + (threadIdx.x >> 5)) * ROWS_PER_WARP;

    // Front-batched loads: 8 tile rows + 1 prev row, all independent (MLP=9).
    float4 v[ROWS_PER_WARP];
    #pragma unroll
    for (int k = 0; k < ROWS_PER_WARP; k++) {
        v[k] = reinterpret_cast<const float4*>(em + (size_t)(base + k) * V)[lane];
    }
    float4 pv;
    const bool has_prev = (base > 0);
    if (has_prev) {
        // Last row of the preceding warp's tile: L2-deduplicated fetch.
        pv = reinterpret_cast<const float4*>(em + (size_t)(base - 1) * V)[lane];
    }

    // prev symbol for row 0 of this tile.
    float prev = -1.0f;
    if (has_prev) {
        float pi, pm;
        warp_row_argmax(pv, lane, pi, pm);
        prev = pi;
    }

    float res_idx[ROWS_PER_WARP], kp[ROWS_PER_WARP], sc[ROWS_PER_WARP];

    #pragma unroll
    for (int k = 0; k < ROWS_PER_WARP; k++) {
        float ci, cm;
        warp_row_argmax(v[k], lane, ci, cm);
        bool keep = (ci != prev) && (ci != (float)BLANK);
        res_idx[k] = ci;
        kp[k] = keep ? 1.0f : 0.0f;
        sc[k] = keep ? cm : 0.0f;
        prev = ci;
    }

    if (lane == 0) {
        // base is a multiple of 8 -> 16B-aligned float4 stores
        reinterpret_cast<float4*>(out_idx + base)[0] =
            make_float4(res_idx[0], res_idx[1], res_idx[2], res_idx[3]);
        reinterpret_cast<float4*>(out_idx + base)[1] =
            make_float4(res_idx[4], res_idx[5], res_idx[6], res_idx[7]);
        reinterpret_cast<float4*>(out_keep + base)[0] =
            make_float4(kp[0], kp[1], kp[2], kp[3]);
        reinterpret_cast<float4*>(out_keep + base)[1] =
            make_float4(kp[4], kp[5], kp[6], kp[7]);
        reinterpret_cast<float4*>(out_score + base)[0] =
            make_float4(sc[0], sc[1], sc[2], sc[3]);
        reinterpret_cast<float4*>(out_score + base)[1] =
            make_float4(sc[4], sc[5], sc[6], sc[7]);
    }
}

extern "C" void kernel_launch(void* const* d_in, const int* in_sizes, int n_in,
                              void* d_out, int out_size)
{
    const float* em = (const float*)d_in[0];
    float* out = (float*)d_out;

    const int rows = in_sizes[0] / V;            // T = 1048576 (divisible by 64)
    float* out_idx   = out;                      // [0:T)
    float* out_keep  = out + rows;               // [T:2T)
    float* out_score = out + 2 * (size_t)rows;   // [2T:3T)

    dim3 block(WARPS_PER_BLOCK * 32);            // 256
    dim3 grid(rows / ROWS_PER_BLOCK);            // exact: 16384
    ctc_fused_kernel<<<grid, block>>>(em, out_idx, out_keep, out_score);
}